// round 7
// baseline (speedup 1.0000x reference)
#include <cuda_runtime.h>
#include <stdint.h>

// TestSpatialTransform == two center crops of (4,2,192,192,192) -> (4,2,160,160,160).
// Pure HBM copy at minimum traffic (524 MB); measured plateau ~6.6 TB/s.
// Shape locked from sweep: thread = one float4, lanes contiguous (warp=512B),
// MLP=2 (data+seg same index). This round adds a software-pipelined
// grid-stride loop: next iteration's loads issue BEFORE current stores, so
// 4 loads stay in flight continuously with ~26 regs / high occupancy.

#define PATCH 160
#define SRC   192
#define OFF   16
#define W4    (PATCH / 4)                          // 40 float4 per row
#define N_F4  (8 * PATCH * PATCH * W4)             // 8,192,000 per tensor
#define THREADS 256
#define BLOCKS  4000
#define STRIDE  (THREADS * BLOCKS)                 // 1,024,000
#define ITERS   (N_F4 / STRIDE)                    // 8 exactly

__device__ __forceinline__ int src_index(int idx)
{
    int w4 = idx % W4;
    int t  = idx / W4;
    int h  = t % PATCH; t /= PATCH;
    int d  = t % PATCH;
    int bc = t / PATCH;
    return (((bc * SRC) + (d + OFF)) * SRC + (h + OFF)) * SRC + OFF + (w4 << 2);
}

__global__ void __launch_bounds__(THREADS)
crop_copy_pipe_kernel(const float* __restrict__ data,
                      const float* __restrict__ seg,
                      float4* __restrict__ out)
{
    int idx = blockIdx.x * THREADS + threadIdx.x;

    int sidx = src_index(idx);
    float4 a = __ldcs(reinterpret_cast<const float4*>(data + sidx));
    float4 b = __ldcs(reinterpret_cast<const float4*>(seg  + sidx));

#pragma unroll
    for (int it = 0; it < ITERS - 1; it++) {
        int nidx = idx + STRIDE;
        int nsidx = src_index(nidx);
        // prefetch next iteration's loads before draining current stores
        float4 a2 = __ldcs(reinterpret_cast<const float4*>(data + nsidx));
        float4 b2 = __ldcs(reinterpret_cast<const float4*>(seg  + nsidx));

        __stcs(out + idx,        a);
        __stcs(out + idx + N_F4, b);

        a = a2; b = b2; idx = nidx;
    }

    __stcs(out + idx,        a);
    __stcs(out + idx + N_F4, b);
}

extern "C" void kernel_launch(void* const* d_in, const int* in_sizes, int n_in,
                              void* d_out, int out_size)
{
    const float* data = (const float*)d_in[0];
    const float* seg  = (const float*)d_in[1];
    float4* out = (float4*)d_out;

    crop_copy_pipe_kernel<<<BLOCKS, THREADS>>>(data, seg, out);
}

// round 8
// speedup vs baseline: 1.0263x; 1.0263x over previous
#include <cuda_runtime.h>
#include <stdint.h>

// TestSpatialTransform == two center crops:
//   out[0:N)   = data[:, :, 16:176, 16:176, 16:176]
//   out[N:2N)  = seg [:, :, 16:176, 16:176, 16:176]
// Pure HBM copy at minimum traffic (524 MB). Empirical optimum from a 7-round
// sweep (MLP 1/2/4/16, block 256/512, thread-contig, bc-spread, sw-pipeline):
// MLP=2 per thread (data+seg at the same crop index), one float4 per thread,
// lane-contiguous warps (512 B/warp/tensor), 256-thread blocks, one-shot.
// Achieves 6.64 TB/s = HBM mixed read/write turnaround ceiling (~83% of spec).

#define PATCH 160
#define SRC   192
#define OFF   16
#define W4    (PATCH / 4)              // 40 float4 per row
#define N_F4_PER_TENSOR (8 * PATCH * PATCH * W4)   // 8,192,000

__global__ void __launch_bounds__(256)
crop_copy2_kernel(const float* __restrict__ data,
                  const float* __restrict__ seg,
                  float4* __restrict__ out)
{
    int idx = blockIdx.x * blockDim.x + threadIdx.x;
    if (idx >= N_F4_PER_TENSOR) return;

    int w4 = idx % W4;
    int t  = idx / W4;
    int h  = t % PATCH; t /= PATCH;
    int d  = t % PATCH;
    int bc = t / PATCH;

    // source flat float index within (8, 192, 192, 192)
    int sidx = (((bc * SRC) + (d + OFF)) * SRC + (h + OFF)) * SRC + OFF + (w4 << 2);

    // two independent streaming loads (deep L1tex queue), then two stores
    float4 a = __ldcs(reinterpret_cast<const float4*>(data + sidx));
    float4 b = __ldcs(reinterpret_cast<const float4*>(seg  + sidx));

    __stcs(out + idx, a);
    __stcs(out + idx + N_F4_PER_TENSOR, b);
}

extern "C" void kernel_launch(void* const* d_in, const int* in_sizes, int n_in,
                              void* d_out, int out_size)
{
    const float* data = (const float*)d_in[0];
    const float* seg  = (const float*)d_in[1];
    float4* out = (float4*)d_out;

    const int threads = 256;
    const int blocks  = (N_F4_PER_TENSOR + threads - 1) / threads;  // 32000
    crop_copy2_kernel<<<blocks, threads>>>(data, seg, out);
}